// round 6
// baseline (speedup 1.0000x reference)
#include <cuda_runtime.h>
#include <cstdint>
#include <cstddef>

#define BATCH   16
#define LSEQ    4096
#define INDIM   64
#define DMODEL  128
#define OUTDIM  64
#define TCHUNK  128
#define NCHUNK  32          // LSEQ / TCHUNK
#define CHAINS  256         // 128 p * {re,im}
#define MTILE   256         // kD rows per CTA (2 chunks)

// ---------------- device scratch (no allocations allowed) ----------------
__device__ float  g_w[(size_t)BATCH * LSEQ * CHAINS];        // local-scan w (67MB)
__device__ float2 g_carry[BATCH * NCHUNK * CHAINS];          // chunk-local final states
__device__ float2 g_cin[BATCH * NCHUNK * CHAINS];            // exclusive cross-chunk prefix
__device__ float  g_BW[CHAINS * INDIM];                      // fused B_part * W_in
__device__ float  g_BuC[CHAINS];                             // B_part * b_in
__device__ float4 g_Pm[TCHUNK * DMODEL];                     // M^{j+1} per p: {m11,m12,m21,m22}
__device__ float  g_WcT[320 * OUTDIM];                       // fused output matrix, [k][o]
__device__ float  g_bias[OUTDIM];

// ---------------- f32x2 / smem helpers ----------------
__device__ __forceinline__ unsigned long long pack2(float lo, float hi) {
    unsigned long long r;
    asm("mov.b64 %0, {%1, %2};" : "=l"(r) : "f"(lo), "f"(hi));
    return r;
}
__device__ __forceinline__ float2 unpack2(unsigned long long v) {
    float lo, hi;
    asm("mov.b64 {%0, %1}, %2;" : "=f"(lo), "=f"(hi) : "l"(v));
    return make_float2(lo, hi);
}
__device__ __forceinline__ unsigned long long fma2(unsigned long long a, unsigned long long b, unsigned long long c) {
    unsigned long long d;
    asm("fma.rn.f32x2 %0, %1, %2, %3;" : "=l"(d) : "l"(a), "l"(b), "l"(c));
    return d;
}
__device__ __forceinline__ unsigned long long add2(unsigned long long a, unsigned long long b) {
    unsigned long long d;
    asm("add.rn.f32x2 %0, %1, %2;" : "=l"(d) : "l"(a), "l"(b));
    return d;
}
__device__ __forceinline__ void lds_v2u64(unsigned long long &a, unsigned long long &b, uint32_t addr) {
    asm volatile("ld.shared.v2.u64 {%0, %1}, [%2];" : "=l"(a), "=l"(b) : "r"(addr));
}
__device__ __forceinline__ void sts_u64(uint32_t addr, unsigned long long v) {
    asm volatile("st.shared.b64 [%0], %1;" :: "r"(addr), "l"(v));
}
__device__ __forceinline__ void sts_v4f(uint32_t addr, float4 v) {
    asm volatile("st.shared.v4.f32 [%0], {%1, %2, %3, %4};"
                 :: "r"(addr), "f"(v.x), "f"(v.y), "f"(v.z), "f"(v.w));
}
__device__ __forceinline__ uint32_t smem_u32(const void* p) {
    uint32_t a;
    asm("{ .reg .u64 t; cvta.to.shared.u64 t, %1; cvt.u32.u64 %0, t; }" : "=r"(a) : "l"(p));
    return a;
}
__device__ __forceinline__ float shfl_bfly1(float v) {
    float r;
    asm volatile("shfl.sync.bfly.b32 %0, %1, 1, 0x1f, 0xffffffff;" : "=f"(r) : "f"(v));
    return r;
}

// implicit-LinOSS per-p recurrence coefficients
__device__ __forceinline__ void lin_coefs(const float* __restrict__ A_diag,
                                          const float* __restrict__ steps, int p,
                                          float& m11, float& m12, float& m21, float& m22,
                                          float& f1, float& f2) {
    float A  = fmaxf(A_diag[p], 0.0f);
    float dt = 1.0f / (1.0f + expf(-steps[p]));
    float dt2A = dt * dt * A;
    float S  = 1.0f / (1.0f + dt2A);
    m11 = 1.0f - dt2A * S;
    m12 = -dt * A * S;
    m21 = dt * S;
    m22 = S;
    f1  = m11 * dt;
    f2  = m21 * dt;
}

// ================= kernel A: build fused matrices + power table =================
__global__ __launch_bounds__(256) void kA(const float* __restrict__ W_in,
                                          const float* __restrict__ b_in,
                                          const float* __restrict__ A_diag,
                                          const float* __restrict__ Bmat,
                                          const float* __restrict__ Cmat,
                                          const float* __restrict__ Dvec,
                                          const float* __restrict__ steps,
                                          const float* __restrict__ W_out,
                                          const float* __restrict__ b_out) {
    __shared__ float sbuf[11264];
    const int bid = blockIdx.x, tid = threadIdx.x;

    if (bid < 16) {
        float* Wins = sbuf;                   // [128][64]
        float* Bs   = sbuf + DMODEL * INDIM;  // [16][128]
        for (int i = tid; i < DMODEL * INDIM; i += 256) Wins[i] = W_in[i];
        const int k0 = bid * 16;
        for (int i = tid; i < 16 * DMODEL; i += 256) {
            int kk = i >> 7, h = i & 127;
            int k = k0 + kk, p = k & 127, part = k >> 7;
            Bs[i] = Bmat[(p * DMODEL + h) * 2 + part];
        }
        __syncthreads();
        for (int e = tid; e < 16 * INDIM; e += 256) {
            int kk = e >> 6, i = e & 63;
            float acc = 0.0f;
            #pragma unroll 8
            for (int h = 0; h < DMODEL; h++) acc = fmaf(Bs[kk * DMODEL + h], Wins[h * INDIM + i], acc);
            g_BW[(k0 + kk) * INDIM + i] = acc;
        }
        if (bid == 0) {
            int k = tid, p = k & 127, part = k >> 7;
            float s = 0.0f;
            for (int h = 0; h < DMODEL; h++) s = fmaf(Bmat[(p * DMODEL + h) * 2 + part], b_in[h], s);
            g_BuC[k] = s;
        }
    } else if (bid < 32) {
        float* Wos = sbuf;                    // [64][129] padded
        float* Cs  = sbuf + OUTDIM * 129;     // [20][128]
        for (int i = tid; i < OUTDIM * DMODEL; i += 256) {
            int o = i >> 7, h = i & 127;
            Wos[o * 129 + h] = W_out[i];
        }
        const int kb0 = (bid - 16) * 20;
        for (int i = tid; i < 20 * DMODEL; i += 256) {
            int kk = i >> 7, h = i & 127;
            int k = kb0 + kk;
            float v;
            if (k < 128)      v =  Cmat[(h * DMODEL + k) * 2 + 0];
            else if (k < 256) v = -Cmat[(h * DMODEL + (k - 128)) * 2 + 1];
            else              v =  Dvec[h] * W_in[h * INDIM + (k - 256)];
            Cs[i] = v;
        }
        __syncthreads();
        for (int e = tid; e < 20 * OUTDIM; e += 256) {
            int kk = e >> 6, o = e & 63;
            float acc = 0.0f;
            #pragma unroll 8
            for (int h = 0; h < DMODEL; h++) acc = fmaf(Cs[kk * DMODEL + h], Wos[o * 129 + h], acc);
            g_WcT[(kb0 + kk) * OUTDIM + o] = acc;
        }
        if (bid == 16 && tid < OUTDIM) {
            float s = b_out[tid];
            for (int h = 0; h < DMODEL; h++) s = fmaf(W_out[tid * DMODEL + h] * Dvec[h], b_in[h], s);
            g_bias[tid] = s;
        }
    } else {
        if (tid < DMODEL) {
            float m11, m12, m21, m22, f1, f2;
            lin_coefs(A_diag, steps, tid, m11, m12, m21, m22, f1, f2);
            float c11 = m11, c12 = m12, c21 = m21, c22 = m22;
            for (int j = 0; j < TCHUNK; j++) {
                g_Pm[j * DMODEL + tid] = make_float4(c11, c12, c21, c22);
                float n11 = m11 * c11 + m12 * c21;
                float n12 = m11 * c12 + m12 * c22;
                float n21 = m21 * c11 + m22 * c21;
                float n22 = m21 * c12 + m22 * c22;
                c11 = n11; c12 = n12; c21 = n21; c22 = n22;
            }
        }
    }
}

// ================= kernel B: fused Bu-GEMM + chunk-local scan (split-K x2) =================
// 256 threads = 128 chains x 2 K-halves. Partners = adjacent lanes (shfl.bfly 1).
// Grid: BATCH * NCHUNK * 2 (chain half per CTA).
__global__ __launch_bounds__(256) void kB(const float* __restrict__ x,
                                          const float* __restrict__ A_diag,
                                          const float* __restrict__ steps) {
    __shared__ float4 xs4[TCHUNK * INDIM / 4];   // 32KB x tile
    const int b  = blockIdx.x >> 6;
    const int c  = (blockIdx.x >> 1) & 31;
    const int bh = blockIdx.x & 1;               // chain half
    const int tid = threadIdx.x;

    const float4* xg = (const float4*)(x + (size_t)(b * LSEQ + c * TCHUNK) * INDIM);
    #pragma unroll
    for (int i = 0; i < 8; i++) xs4[tid + i * 256] = xg[tid + i * 256];

    const int kl = tid >> 1;            // local chain 0..127
    const int h  = tid & 1;             // K half
    const int k  = bh * 128 + kl;       // global chain
    const int p  = k & 127;
    float m11, m12, m21, m22, f1, f2;
    lin_coefs(A_diag, steps, p, m11, m12, m21, m22, f1, f2);

    // BW half-row (32 floats) pre-packed for f32x2
    unsigned long long bw2[16];
    {
        const float4* br = (const float4*)(g_BW + k * INDIM + h * 32);
        #pragma unroll
        for (int i = 0; i < 8; i++) {
            float4 v = br[i];
            bw2[2 * i]     = pack2(v.x, v.y);
            bw2[2 * i + 1] = pack2(v.z, v.w);
        }
    }
    const float buc = g_BuC[k];
    __syncthreads();

    const uint32_t xsb = smem_u32(xs4) + h * 128;
    float z = 0.0f, w = 0.0f;
    float* wout = g_w + (size_t)(b * LSEQ + c * TCHUNK) * CHAINS + k;

    for (int t = 0; t < TCHUNK; t += 4) {
        float bu[4];
        #pragma unroll
        for (int u = 0; u < 4; u++) {
            const uint32_t base = xsb + (t + u) * 256;
            unsigned long long a0 = 0ull, a1 = 0ull;
            #pragma unroll
            for (int i = 0; i < 4; i++) {
                unsigned long long xA, xB, xC, xD;
                lds_v2u64(xA, xB, base + i * 32);
                lds_v2u64(xC, xD, base + i * 32 + 16);
                a0 = fma2(bw2[4 * i],     xA, a0);
                a1 = fma2(bw2[4 * i + 1], xB, a1);
                a0 = fma2(bw2[4 * i + 2], xC, a0);
                a1 = fma2(bw2[4 * i + 3], xD, a1);
            }
            float2 sf = unpack2(add2(a0, a1));
            float ps = sf.x + sf.y;
            float po = shfl_bfly1(ps);
            bu[u] = ps + po + buc;
        }
        #pragma unroll
        for (int u = 0; u < 4; u++) {
            float nz = fmaf(m11, z, fmaf(m12, w, f1 * bu[u]));
            float nw = fmaf(m21, z, fmaf(m22, w, f2 * bu[u]));
            z = nz; w = nw;
            if ((u & 1) == h) wout[(size_t)(t + u) * CHAINS] = w;
        }
    }
    if (h == 0) g_carry[(b * NCHUNK + c) * CHAINS + k] = make_float2(z, w);
}

// ================= kernel C: cross-chunk scan of carries (prefetched) =================
__global__ __launch_bounds__(256) void kC() {
    const int b = blockIdx.x, k = threadIdx.x, p = k & 127;
    const float4 mt = g_Pm[(TCHUNK - 1) * DMODEL + p];   // M^TCHUNK
    float z = 0.0f, w = 0.0f;
    for (int c0 = 0; c0 < NCHUNK; c0 += 8) {
        float2 lc[8];
        #pragma unroll
        for (int j = 0; j < 8; j++)
            lc[j] = g_carry[(b * NCHUNK + c0 + j) * CHAINS + k];
        #pragma unroll
        for (int j = 0; j < 8; j++) {
            g_cin[(b * NCHUNK + c0 + j) * CHAINS + k] = make_float2(z, w);
            float nz = fmaf(mt.x, z, fmaf(mt.y, w, lc[j].x));
            float nw = fmaf(mt.z, z, fmaf(mt.w, w, lc[j].y));
            z = nz; w = nw;
        }
    }
}

// ================= kernel D: carry fixup + fused output GEMM (f32x2, 8x8 tiles) =================
// out[t][o] = sum_k [w_re | w_im | x][t][k] * WcT[k][o] + bias[o],  K=320, staged 16 kk/step.
// A plain float [kk][256 rows], 16B granules XOR-swizzled by (kk&7)  -> conflict-free both ways.
// B duplicated u64 [kk][64 cols], granules XOR-swizzled (standard)   -> conflict-free both ways.
__global__ __launch_bounds__(256, 2) void kD(const float* __restrict__ x,
                                             float* __restrict__ out) {
    __shared__ float As[16 * 256];                  // 16KB
    __shared__ unsigned long long Bsd[16 * 64];     // 8KB
    __shared__ float czs[2 * 256], cws[2 * 256];    // 4KB
    const int blk = blockIdx.x;
    const int R0  = blk * MTILE;        // global row (b*LSEQ + t0)
    const int b   = R0 >> 12;
    const int t0  = R0 & 4095;
    const int c0  = t0 >> 7;            // chunks c0, c0+1
    const int tid = threadIdx.x;

    {
        float2 ci0 = g_cin[(b * NCHUNK + c0) * CHAINS + tid];
        float2 ci1 = g_cin[(b * NCHUNK + c0 + 1) * CHAINS + tid];
        czs[tid] = ci0.x;       cws[tid] = ci0.y;
        czs[256 + tid] = ci1.x; cws[256 + tid] = ci1.y;
    }

    const int tx = tid & 7,  ty = tid >> 3;      // compute: 8 col-groups x 32 row-groups
    const int kks = tid & 15, rseg = tid >> 4;   // staging: 16 kk x 16 row-segments (16 rows each)
    const int g0 = ty * 2;

    // acc[rp][cc]: row pair (ty*8+2rp, +1), col tx*8+cc; init = dup(bias)
    unsigned long long acc[4][8];
    {
        #pragma unroll
        for (int cc = 0; cc < 8; cc++) {
            float bv = g_bias[tx * 8 + cc];
            unsigned long long bd = pack2(bv, bv);
            #pragma unroll
            for (int rp = 0; rp < 4; rp++) acc[rp][cc] = bd;
        }
    }

    const uint32_t sA = smem_u32(As);
    const uint32_t sB = smem_u32(Bsd);

    // kk-invariant swizzled B granule offsets for this thread
    uint32_t offB[4];
    {
        int keyB = tx >> 1;
        #pragma unroll
        for (int jj = 0; jj < 4; jj++)
            offB[jj] = (uint32_t)(((tx * 4) | (jj ^ keyB)) << 4);
    }

    for (int s = 0; s < 20; s++) {
        __syncthreads();
        // ---- stage B: 16 kk x 64 cols, duplicated + swizzled ----
        {
            int kkB = tid >> 4, cb0 = (tid & 15) * 4;
            const float* src = g_WcT + (s * 16 + kkB) * OUTDIM + cb0;
            float4 v = *(const float4*)src;
            float vv[4] = {v.x, v.y, v.z, v.w};
            #pragma unroll
            for (int i = 0; i < 4; i++) {
                int cthis = cb0 + i;
                int G = cthis >> 1;
                int phys = G ^ ((G >> 3) & 7);
                sts_u64(sB + kkB * 512 + (phys << 4) + (cthis & 1) * 8, pack2(vv[i], vv[i]));
            }
        }
        // ---- stage A: 16 kk x 256 rows (fixup for s<16, x passthrough for s>=16) ----
        if (s < 16) {
            const int kGlob = s * 16 + kks;
            const int p = kGlob & 127;
            const int ch = rseg >> 3;
            const float cz = czs[ch * 256 + kGlob], cw = cws[ch * 256 + kGlob];
            const float* wsrc = g_w + (size_t)R0 * CHAINS + kGlob;
            #pragma unroll
            for (int q = 0; q < 4; q++) {
                float vals[4];
                #pragma unroll
                for (int e = 0; e < 4; e++) {
                    int r = rseg * 16 + q * 4 + e;
                    int j = r & 127;
                    float4 pm = g_Pm[j * DMODEL + p];
                    vals[e] = fmaf(pm.z, cz, fmaf(pm.w, cw, wsrc[(size_t)r * CHAINS]));
                }
                int g = rseg * 4 + q;
                uint32_t addr = sA + kks * 1024 + (uint32_t)((g ^ (kks & 7)) << 4);
                sts_v4f(addr, make_float4(vals[0], vals[1], vals[2], vals[3]));
            }
        } else {
            const int xi = (s - 16) * 16 + kks;
            const float* xsrc = x + (size_t)R0 * INDIM + xi;
            #pragma unroll
            for (int q = 0; q < 4; q++) {
                float vals[4];
                #pragma unroll
                for (int e = 0; e < 4; e++) {
                    int r = rseg * 16 + q * 4 + e;
                    vals[e] = xsrc[(size_t)r * INDIM];
                }
                int g = rseg * 4 + q;
                uint32_t addr = sA + kks * 1024 + (uint32_t)((g ^ (kks & 7)) << 4);
                sts_v4f(addr, make_float4(vals[0], vals[1], vals[2], vals[3]));
            }
        }
        __syncthreads();
        // ---- compute: 16 kk, per kk: 6 LDS + 32 fma2 ----
        #pragma unroll
        for (int kk = 0; kk < 16; kk++) {
            const uint32_t akey = (uint32_t)((kk & 7) << 4);
            unsigned long long pr[4];
            lds_v2u64(pr[0], pr[1], sA + kk * 1024 + (((uint32_t)g0 << 4) ^ akey));
            lds_v2u64(pr[2], pr[3], sA + kk * 1024 + (((uint32_t)(g0 + 1) << 4) ^ akey));
            unsigned long long bq[8];
            lds_v2u64(bq[0], bq[1], sB + kk * 512 + offB[0]);
            lds_v2u64(bq[2], bq[3], sB + kk * 512 + offB[1]);
            lds_v2u64(bq[4], bq[5], sB + kk * 512 + offB[2]);
            lds_v2u64(bq[6], bq[7], sB + kk * 512 + offB[3]);
            #pragma unroll
            for (int rp = 0; rp < 4; rp++) {
                #pragma unroll
                for (int cc = 0; cc < 8; cc++)
                    acc[rp][cc] = fma2(pr[rp], bq[cc], acc[rp][cc]);
            }
        }
    }

    // epilogue: unpack row pairs -> 2 float4 stores per row
    float* og = out + (size_t)R0 * OUTDIM + tx * 8;
    #pragma unroll
    for (int rp = 0; rp < 4; rp++) {
        float2 u0 = unpack2(acc[rp][0]);
        float2 u1 = unpack2(acc[rp][1]);
        float2 u2 = unpack2(acc[rp][2]);
        float2 u3 = unpack2(acc[rp][3]);
        float2 u4 = unpack2(acc[rp][4]);
        float2 u5 = unpack2(acc[rp][5]);
        float2 u6 = unpack2(acc[rp][6]);
        float2 u7 = unpack2(acc[rp][7]);
        int row = ty * 8 + rp * 2;
        float* r0 = og + (size_t)row * OUTDIM;
        float* r1 = og + (size_t)(row + 1) * OUTDIM;
        *(float4*)(r0)     = make_float4(u0.x, u1.x, u2.x, u3.x);
        *(float4*)(r0 + 4) = make_float4(u4.x, u5.x, u6.x, u7.x);
        *(float4*)(r1)     = make_float4(u0.y, u1.y, u2.y, u3.y);
        *(float4*)(r1 + 4) = make_float4(u4.y, u5.y, u6.y, u7.y);
    }
}

extern "C" void kernel_launch(void* const* d_in, const int* in_sizes, int n_in,
                              void* d_out, int out_size) {
    const float* x      = (const float*)d_in[0];
    const float* W_in   = (const float*)d_in[1];
    const float* b_in   = (const float*)d_in[2];
    const float* A_diag = (const float*)d_in[3];
    const float* Bmat   = (const float*)d_in[4];
    const float* Cmat   = (const float*)d_in[5];
    const float* Dvec   = (const float*)d_in[6];
    const float* steps  = (const float*)d_in[7];
    const float* W_out  = (const float*)d_in[8];
    const float* b_out  = (const float*)d_in[9];
    float* out = (float*)d_out;

    kA<<<33, 256>>>(W_in, b_in, A_diag, Bmat, Cmat, Dvec, steps, W_out, b_out);
    kB<<<BATCH * NCHUNK * 2, 256>>>(x, A_diag, steps);
    kC<<<BATCH, 256>>>();
    kD<<<(BATCH * LSEQ) / MTILE, 256>>>(x, out);
}

// round 8
// speedup vs baseline: 1.7567x; 1.7567x over previous
#include <cuda_runtime.h>
#include <cuda_fp16.h>
#include <cstdint>
#include <cstddef>

#define BATCH   16
#define LSEQ    4096
#define INDIM   64
#define DMODEL  128
#define OUTDIM  64
#define TCHUNK  128
#define NCHUNK  32          // LSEQ / TCHUNK
#define CHAINS  256         // 128 p * {re,im}

// ---------------- device scratch (no allocations allowed) ----------------
__device__ float  g_w[(size_t)BATCH * LSEQ * CHAINS];        // local-scan w (67MB, fp32)
__device__ float2 g_carry[BATCH * NCHUNK * CHAINS];          // chunk-local final states
__device__ float2 g_cin[BATCH * NCHUNK * CHAINS];            // exclusive cross-chunk prefix
__device__ float  g_BW[CHAINS * INDIM];                      // fused B_part * W_in
__device__ float  g_BuC[CHAINS];                             // B_part * b_in
__device__ float4 g_Pm[TCHUNK * DMODEL];                     // M^{j+1} per p (kC uses row TCHUNK-1)
__device__ float2 g_Pzw[TCHUNK * DMODEL];                    // (M^{j+1}).{21,22} per (j,p)  [kD fixup]
__device__ __half g_WcF[OUTDIM * 320];                       // fused output matrix fp16, [o][k]
__device__ float  g_bias[OUTDIM];

// ---------------- helpers ----------------
__device__ __forceinline__ unsigned long long pack2(float lo, float hi) {
    unsigned long long r;
    asm("mov.b64 %0, {%1, %2};" : "=l"(r) : "f"(lo), "f"(hi));
    return r;
}
__device__ __forceinline__ float2 unpack2(unsigned long long v) {
    float lo, hi;
    asm("mov.b64 {%0, %1}, %2;" : "=f"(lo), "=f"(hi) : "l"(v));
    return make_float2(lo, hi);
}
__device__ __forceinline__ unsigned long long fma2(unsigned long long a, unsigned long long b, unsigned long long c) {
    unsigned long long d;
    asm("fma.rn.f32x2 %0, %1, %2, %3;" : "=l"(d) : "l"(a), "l"(b), "l"(c));
    return d;
}
__device__ __forceinline__ unsigned long long add2(unsigned long long a, unsigned long long b) {
    unsigned long long d;
    asm("add.rn.f32x2 %0, %1, %2;" : "=l"(d) : "l"(a), "l"(b));
    return d;
}
__device__ __forceinline__ void lds_v2u64(unsigned long long &a, unsigned long long &b, uint32_t addr) {
    asm volatile("ld.shared.v2.u64 {%0, %1}, [%2];" : "=l"(a), "=l"(b) : "r"(addr));
}
__device__ __forceinline__ uint32_t smem_u32(const void* p) {
    uint32_t a;
    asm("{ .reg .u64 t; cvta.to.shared.u64 t, %1; cvt.u32.u64 %0, t; }" : "=r"(a) : "l"(p));
    return a;
}
__device__ __forceinline__ void ldsm_x4(uint32_t &r0, uint32_t &r1, uint32_t &r2, uint32_t &r3, uint32_t addr) {
    asm volatile("ldmatrix.sync.aligned.m8n8.x4.shared.b16 {%0,%1,%2,%3}, [%4];"
                 : "=r"(r0), "=r"(r1), "=r"(r2), "=r"(r3) : "r"(addr));
}
__device__ __forceinline__ void mma16816(float &c0, float &c1, float &c2, float &c3,
                                         uint32_t a0, uint32_t a1, uint32_t a2, uint32_t a3,
                                         uint32_t b0, uint32_t b1) {
    asm volatile("mma.sync.aligned.m16n8k16.row.col.f32.f16.f16.f32 "
                 "{%0,%1,%2,%3}, {%4,%5,%6,%7}, {%8,%9}, {%0,%1,%2,%3};"
                 : "+f"(c0), "+f"(c1), "+f"(c2), "+f"(c3)
                 : "r"(a0), "r"(a1), "r"(a2), "r"(a3), "r"(b0), "r"(b1));
}

// implicit-LinOSS per-p recurrence coefficients
__device__ __forceinline__ void lin_coefs(const float* __restrict__ A_diag,
                                          const float* __restrict__ steps, int p,
                                          float& m11, float& m12, float& m21, float& m22,
                                          float& f1, float& f2) {
    float A  = fmaxf(A_diag[p], 0.0f);
    float dt = 1.0f / (1.0f + expf(-steps[p]));
    float dt2A = dt * dt * A;
    float S  = 1.0f / (1.0f + dt2A);
    m11 = 1.0f - dt2A * S;
    m12 = -dt * A * S;
    m21 = dt * S;
    m22 = S;
    f1  = m11 * dt;
    f2  = m21 * dt;
}

// ================= kernel A: build fused matrices + power tables =================
__global__ __launch_bounds__(256) void kA(const float* __restrict__ W_in,
                                          const float* __restrict__ b_in,
                                          const float* __restrict__ A_diag,
                                          const float* __restrict__ Bmat,
                                          const float* __restrict__ Cmat,
                                          const float* __restrict__ Dvec,
                                          const float* __restrict__ steps,
                                          const float* __restrict__ W_out,
                                          const float* __restrict__ b_out) {
    __shared__ float sbuf[11264];
    const int bid = blockIdx.x, tid = threadIdx.x;

    if (bid < 16) {
        // BW[k][i] = sum_h B_part[k][h] * W_in[h][i]; 16 k-rows per block
        float* Wins = sbuf;                   // [128][64]
        float* Bs   = sbuf + DMODEL * INDIM;  // [16][128]
        for (int i = tid; i < DMODEL * INDIM; i += 256) Wins[i] = W_in[i];
        const int k0 = bid * 16;
        for (int i = tid; i < 16 * DMODEL; i += 256) {
            int kk = i >> 7, h = i & 127;
            int k = k0 + kk, p = k & 127, part = k >> 7;
            Bs[i] = Bmat[(p * DMODEL + h) * 2 + part];
        }
        __syncthreads();
        for (int e = tid; e < 16 * INDIM; e += 256) {
            int kk = e >> 6, i = e & 63;
            float acc = 0.0f;
            #pragma unroll 8
            for (int h = 0; h < DMODEL; h++) acc = fmaf(Bs[kk * DMODEL + h], Wins[h * INDIM + i], acc);
            g_BW[(k0 + kk) * INDIM + i] = acc;
        }
        if (bid == 0) {
            int k = tid, p = k & 127, part = k >> 7;
            float s = 0.0f;
            for (int h = 0; h < DMODEL; h++) s = fmaf(Bmat[(p * DMODEL + h) * 2 + part], b_in[h], s);
            g_BuC[k] = s;
        }
    } else if (bid < 32) {
        // Wc rows: k<128: W_out*C_re ; k<256: -W_out*C_im ; else W_out*diag(D)*W_in
        // store fp16 as [o][k]
        float* Wos = sbuf;                    // [64][129] padded
        float* Cs  = sbuf + OUTDIM * 129;     // [20][128]
        for (int i = tid; i < OUTDIM * DMODEL; i += 256) {
            int o = i >> 7, h = i & 127;
            Wos[o * 129 + h] = W_out[i];
        }
        const int kb0 = (bid - 16) * 20;
        for (int i = tid; i < 20 * DMODEL; i += 256) {
            int kk = i >> 7, h = i & 127;
            int k = kb0 + kk;
            float v;
            if (k < 128)      v =  Cmat[(h * DMODEL + k) * 2 + 0];
            else if (k < 256) v = -Cmat[(h * DMODEL + (k - 128)) * 2 + 1];
            else              v =  Dvec[h] * W_in[h * INDIM + (k - 256)];
            Cs[i] = v;
        }
        __syncthreads();
        for (int e = tid; e < 20 * OUTDIM; e += 256) {
            int kk = e >> 6, o = e & 63;
            float acc = 0.0f;
            #pragma unroll 8
            for (int h = 0; h < DMODEL; h++) acc = fmaf(Cs[kk * DMODEL + h], Wos[o * 129 + h], acc);
            g_WcF[o * 320 + (kb0 + kk)] = __float2half(acc);
        }
        if (bid == 16 && tid < OUTDIM) {
            float s = b_out[tid];
            for (int h = 0; h < DMODEL; h++) s = fmaf(W_out[tid * DMODEL + h] * Dvec[h], b_in[h], s);
            g_bias[tid] = s;
        }
    } else {
        // power tables Pm[j][p] = M^{j+1}; Pzw = rows (21,22)
        if (tid < DMODEL) {
            float m11, m12, m21, m22, f1, f2;
            lin_coefs(A_diag, steps, tid, m11, m12, m21, m22, f1, f2);
            float c11 = m11, c12 = m12, c21 = m21, c22 = m22;
            for (int j = 0; j < TCHUNK; j++) {
                g_Pm[j * DMODEL + tid]  = make_float4(c11, c12, c21, c22);
                g_Pzw[j * DMODEL + tid] = make_float2(c21, c22);
                float n11 = m11 * c11 + m12 * c21;
                float n12 = m11 * c12 + m12 * c22;
                float n21 = m21 * c11 + m22 * c21;
                float n22 = m21 * c12 + m22 * c22;
                c11 = n11; c12 = n12; c21 = n21; c22 = n22;
            }
        }
    }
}

// ================= kernel B: fused Bu-GEMM + chunk-local scan (R5 form) =================
__global__ __launch_bounds__(256) void kB(const float* __restrict__ x,
                                          const float* __restrict__ A_diag,
                                          const float* __restrict__ steps) {
    __shared__ float4 xs4[TCHUNK * INDIM / 4];   // 32KB x tile
    const int b = blockIdx.x >> 5, c = blockIdx.x & 31;
    const int tid = threadIdx.x;

    const float4* xg = (const float4*)(x + (size_t)(b * LSEQ + c * TCHUNK) * INDIM);
    #pragma unroll
    for (int i = 0; i < 8; i++) xs4[tid + i * 256] = xg[tid + i * 256];

    const int k = tid, p = k & 127;
    float m11, m12, m21, m22, f1, f2;
    lin_coefs(A_diag, steps, p, m11, m12, m21, m22, f1, f2);

    unsigned long long bw2[32];
    {
        const float4* br = (const float4*)(g_BW + k * INDIM);
        #pragma unroll
        for (int i = 0; i < 16; i++) {
            float4 v = br[i];
            bw2[2 * i]     = pack2(v.x, v.y);
            bw2[2 * i + 1] = pack2(v.z, v.w);
        }
    }
    const float buc = g_BuC[k];
    __syncthreads();

    const uint32_t xsb = smem_u32(xs4);
    float z = 0.0f, w = 0.0f;
    float* wout = g_w + (size_t)(b * LSEQ + c * TCHUNK) * CHAINS + k;

    for (int t = 0; t < TCHUNK; t += 2) {
        unsigned long long a0 = 0ull, a1 = 0ull, a2 = 0ull, a3 = 0ull;
        unsigned long long c0 = 0ull, c1 = 0ull, c2 = 0ull, c3 = 0ull;
        const uint32_t baseA = xsb + t * 256;
        const uint32_t baseB = baseA + 256;
        #pragma unroll
        for (int i = 0; i < 8; i++) {
            unsigned long long xA, xB, xC, xD, yA, yB, yC, yD;
            lds_v2u64(xA, xB, baseA + i * 32);
            lds_v2u64(xC, xD, baseA + i * 32 + 16);
            lds_v2u64(yA, yB, baseB + i * 32);
            lds_v2u64(yC, yD, baseB + i * 32 + 16);
            a0 = fma2(bw2[4 * i],     xA, a0);
            a1 = fma2(bw2[4 * i + 1], xB, a1);
            a2 = fma2(bw2[4 * i + 2], xC, a2);
            a3 = fma2(bw2[4 * i + 3], xD, a3);
            c0 = fma2(bw2[4 * i],     yA, c0);
            c1 = fma2(bw2[4 * i + 1], yB, c1);
            c2 = fma2(bw2[4 * i + 2], yC, c2);
            c3 = fma2(bw2[4 * i + 3], yD, c3);
        }
        float2 sf0 = unpack2(add2(add2(a0, a1), add2(a2, a3)));
        float2 sf1 = unpack2(add2(add2(c0, c1), add2(c2, c3)));
        float bu0 = sf0.x + sf0.y + buc;
        float bu1 = sf1.x + sf1.y + buc;
        float nz = fmaf(m11, z, fmaf(m12, w, f1 * bu0));
        float nw = fmaf(m21, z, fmaf(m22, w, f2 * bu0));
        wout[(size_t)t * CHAINS] = nw;
        z = fmaf(m11, nz, fmaf(m12, nw, f1 * bu1));
        w = fmaf(m21, nz, fmaf(m22, nw, f2 * bu1));
        wout[(size_t)(t + 1) * CHAINS] = w;
    }
    g_carry[(b * NCHUNK + c) * CHAINS + k] = make_float2(z, w);
}

// ================= kernel C: cross-chunk scan of carries (prefetched) =================
__global__ __launch_bounds__(256) void kC() {
    const int b = blockIdx.x, k = threadIdx.x, p = k & 127;
    const float4 mt = g_Pm[(TCHUNK - 1) * DMODEL + p];   // M^TCHUNK
    float z = 0.0f, w = 0.0f;
    for (int c0 = 0; c0 < NCHUNK; c0 += 8) {
        float2 lc[8];
        #pragma unroll
        for (int j = 0; j < 8; j++)
            lc[j] = g_carry[(b * NCHUNK + c0 + j) * CHAINS + k];
        #pragma unroll
        for (int j = 0; j < 8; j++) {
            g_cin[(b * NCHUNK + c0 + j) * CHAINS + k] = make_float2(z, w);
            float nz = fmaf(mt.x, z, fmaf(mt.y, w, lc[j].x));
            float nw = fmaf(mt.z, z, fmaf(mt.w, w, lc[j].y));
            z = nz; w = nw;
        }
    }
}

// ================= kernel D: carry fixup + output GEMM via mma.sync f16 =================
// C[128 t][64 o] = A[128 t][320 k] * B[64 o][320 k]^T,  fp16 in, fp32 accum.
// K staged in 5 slices of 64. A smem [128][72] fp16, B smem [64][72] fp16 (pad -> conflict-free).
// 8 warps: warp w owns rows 16w..16w+15 x all 64 cols. Per k16: 1 A-ldsm.x4 + 4 B-ldsm.x4 + 8 HMMA.
#define APAD 72
__global__ __launch_bounds__(256) void kD(const float* __restrict__ x,
                                          float* __restrict__ out) {
    __shared__ __half smA[128 * APAD];   // 18KB
    __shared__ __half smB[64 * APAD];    // 9KB
    __shared__ float czs[CHAINS], cws[CHAINS];

    const int R0 = blockIdx.x * 128;          // global row = b*LSEQ + t0
    const int b  = R0 >> 12;
    const int cc = (R0 & 4095) >> 7;          // chunk index
    const int tid = threadIdx.x;
    const int wid = tid >> 5, lane = tid & 31;

    {
        float2 ci = g_cin[(b * NCHUNK + cc) * CHAINS + tid];
        czs[tid] = ci.x; cws[tid] = ci.y;
    }

    const uint32_t sA = smem_u32(smA);
    const uint32_t sB = smem_u32(smB);

    // ldmatrix lane-address components
    const int q  = lane >> 3, rr = lane & 7;
    const uint32_t aBase = sA + (uint32_t)(((wid * 16 + (q & 1) * 8 + rr) * APAD + (q >> 1) * 8) * 2);
    uint32_t bBase[4];
    #pragma unroll
    for (int ntp = 0; ntp < 4; ntp++)
        bBase[ntp] = sB + (uint32_t)(((ntp * 16 + (q >> 1) * 8 + rr) * APAD + (q & 1) * 8) * 2);

    // staging mappings
    const int kp = lane;            // k-pair within slice (k = 2kp, 2kp+1)
    const int rq = wid;             // 16-row segment
    const int brow = tid >> 2, bseg = tid & 3;   // B: row o, 16-half segment

    float acc[8][4];
    #pragma unroll
    for (int nt = 0; nt < 8; nt++)
        #pragma unroll
        for (int i = 0; i < 4; i++) acc[nt][i] = 0.0f;

    for (int s = 0; s < 5; s++) {
        __syncthreads();
        // ---- stage B slice: 64 o-rows x 64 k halves ----
        {
            const uint4* src = (const uint4*)(g_WcF + brow * 320 + s * 64 + bseg * 16);
            uint4 v0 = src[0], v1 = src[1];
            uint4* dst = (uint4*)(smB + brow * APAD + bseg * 16);
            dst[0] = v0; dst[1] = v1;
        }
        // ---- stage A slice: 128 rows x 64 k, carry fixup + cvt fp16 ----
        if (s < 4) {
            const int k2 = kp * 2;
            const int kg = s * 64 + k2;
            const int p0 = kg & 127;
            const float cz0 = czs[kg],     cw0 = cws[kg];
            const float cz1 = czs[kg + 1], cw1 = cws[kg + 1];
            const float* wsrc = g_w + (size_t)R0 * CHAINS + kg;
            #pragma unroll 4
            for (int j = 0; j < 16; j++) {
                int r = rq * 16 + j;
                float4 pz = *(const float4*)(&g_Pzw[r * DMODEL + p0]);  // {z0,w0,z1,w1}
                float2 wv = *(const float2*)(wsrc + (size_t)r * CHAINS);
                float v0 = fmaf(pz.x, cz0, fmaf(pz.y, cw0, wv.x));
                float v1 = fmaf(pz.z, cz1, fmaf(pz.w, cw1, wv.y));
                *(__half2*)(smA + r * APAD + k2) = __floats2half2_rn(v0, v1);
            }
        } else {
            const int k2 = kp * 2;
            const float* xsrc = x + (size_t)R0 * INDIM + k2;
            #pragma unroll 4
            for (int j = 0; j < 16; j++) {
                int r = rq * 16 + j;
                float2 xv = *(const float2*)(xsrc + (size_t)r * INDIM);
                *(__half2*)(smA + r * APAD + k2) = __floats2half2_rn(xv.x, xv.y);
            }
        }
        __syncthreads();

        // ---- compute: 4 k16 steps ----
        #pragma unroll
        for (int k16 = 0; k16 < 4; k16++) {
            const uint32_t kofs = (uint32_t)(k16 * 16 * 2);
            uint32_t a0, a1, a2, a3;
            ldsm_x4(a0, a1, a2, a3, aBase + kofs);
            uint32_t bf[4][4];
            #pragma unroll
            for (int ntp = 0; ntp < 4; ntp++)
                ldsm_x4(bf[ntp][0], bf[ntp][1], bf[ntp][2], bf[ntp][3], bBase[ntp] + kofs);
            #pragma unroll
            for (int ntp = 0; ntp < 4; ntp++) {
                mma16816(acc[ntp * 2][0], acc[ntp * 2][1], acc[ntp * 2][2], acc[ntp * 2][3],
                         a0, a1, a2, a3, bf[ntp][0], bf[ntp][1]);
                mma16816(acc[ntp * 2 + 1][0], acc[ntp * 2 + 1][1], acc[ntp * 2 + 1][2], acc[ntp * 2 + 1][3],
                         a0, a1, a2, a3, bf[ntp][2], bf[ntp][3]);
            }
        }
    }

    // ---- epilogue: add bias, store directly from fragments ----
    const int g = lane >> 2, cpair = (lane & 3) * 2;
    const int row0 = R0 + wid * 16 + g;
    float* og0 = out + (size_t)row0 * OUTDIM;
    float* og1 = og0 + 8 * OUTDIM;
    #pragma unroll
    for (int nt = 0; nt < 8; nt++) {
        int col = nt * 8 + cpair;
        float b0 = g_bias[col], b1 = g_bias[col + 1];
        *(float2*)(og0 + col) = make_float2(acc[nt][0] + b0, acc[nt][1] + b1);
        *(float2*)(og1 + col) = make_float2(acc[nt][2] + b0, acc[nt][3] + b1);
    }
}

extern "C" void kernel_launch(void* const* d_in, const int* in_sizes, int n_in,
                              void* d_out, int out_size) {
    const float* x      = (const float*)d_in[0];
    const float* W_in   = (const float*)d_in[1];
    const float* b_in   = (const float*)d_in[2];
    const float* A_diag = (const float*)d_in[3];
    const float* Bmat   = (const float*)d_in[4];
    const float* Cmat   = (const float*)d_in[5];
    const float* Dvec   = (const float*)d_in[6];
    const float* steps  = (const float*)d_in[7];
    const float* W_out  = (const float*)d_in[8];
    const float* b_out  = (const float*)d_in[9];
    float* out = (float*)d_out;

    kA<<<33, 256>>>(W_in, b_in, A_diag, Bmat, Cmat, Dvec, steps, W_out, b_out);
    kB<<<BATCH * NCHUNK, 256>>>(x, A_diag, steps);
    kC<<<BATCH, 256>>>();
    kD<<<(BATCH * LSEQ) / TCHUNK, 256>>>(x, out);
}

// round 9
// speedup vs baseline: 2.8535x; 1.6244x over previous
#include <cuda_runtime.h>
#include <cuda_fp16.h>
#include <cstdint>
#include <cstddef>

#define BATCH   16
#define LSEQ    4096
#define INDIM   64
#define DMODEL  128
#define OUTDIM  64
#define TCHUNK  128
#define NCHUNK  32          // LSEQ / TCHUNK
#define CHAINS  256         // 128 p * {re,im}

// ---------------- device scratch (no allocations allowed) ----------------
__device__ float  g_w[(size_t)BATCH * LSEQ * CHAINS];        // local-scan w (67MB, fp32)
__device__ float2 g_carry[BATCH * NCHUNK * CHAINS];          // chunk-local final states
__device__ float2 g_cin[BATCH * NCHUNK * CHAINS];            // exclusive cross-chunk prefix
__device__ __half g_BWh[CHAINS * INDIM];                     // fused B_part * W_in (fp16, [k][i])
__device__ float  g_BuC[CHAINS];                             // B_part * b_in
__device__ float4 g_Pm[TCHUNK * DMODEL];                     // M^{j+1} per p (kC uses row TCHUNK-1)
__device__ float2 g_Pzw[TCHUNK * DMODEL];                    // (M^{j+1}).{21,22} per (j,p)  [kD fixup]
__device__ __half g_WcF[OUTDIM * 320];                       // fused output matrix fp16, [o][k]
__device__ float  g_bias[OUTDIM];

// ---------------- helpers ----------------
__device__ __forceinline__ uint32_t smem_u32(const void* p) {
    uint32_t a;
    asm("{ .reg .u64 t; cvta.to.shared.u64 t, %1; cvt.u32.u64 %0, t; }" : "=r"(a) : "l"(p));
    return a;
}
__device__ __forceinline__ void ldsm_x4(uint32_t &r0, uint32_t &r1, uint32_t &r2, uint32_t &r3, uint32_t addr) {
    asm volatile("ldmatrix.sync.aligned.m8n8.x4.shared.b16 {%0,%1,%2,%3}, [%4];"
                 : "=r"(r0), "=r"(r1), "=r"(r2), "=r"(r3) : "r"(addr));
}
__device__ __forceinline__ void mma16816(float &c0, float &c1, float &c2, float &c3,
                                         uint32_t a0, uint32_t a1, uint32_t a2, uint32_t a3,
                                         uint32_t b0, uint32_t b1) {
    asm volatile("mma.sync.aligned.m16n8k16.row.col.f32.f16.f16.f32 "
                 "{%0,%1,%2,%3}, {%4,%5,%6,%7}, {%8,%9}, {%0,%1,%2,%3};"
                 : "+f"(c0), "+f"(c1), "+f"(c2), "+f"(c3)
                 : "r"(a0), "r"(a1), "r"(a2), "r"(a3), "r"(b0), "r"(b1));
}

// implicit-LinOSS per-p recurrence coefficients
__device__ __forceinline__ void lin_coefs(const float* __restrict__ A_diag,
                                          const float* __restrict__ steps, int p,
                                          float& m11, float& m12, float& m21, float& m22,
                                          float& f1, float& f2) {
    float A  = fmaxf(A_diag[p], 0.0f);
    float dt = 1.0f / (1.0f + expf(-steps[p]));
    float dt2A = dt * dt * A;
    float S  = 1.0f / (1.0f + dt2A);
    m11 = 1.0f - dt2A * S;
    m12 = -dt * A * S;
    m21 = dt * S;
    m22 = S;
    f1  = m11 * dt;
    f2  = m21 * dt;
}

// ================= kernel A: build fused matrices + power tables =================
__global__ __launch_bounds__(256) void kA(const float* __restrict__ W_in,
                                          const float* __restrict__ b_in,
                                          const float* __restrict__ A_diag,
                                          const float* __restrict__ Bmat,
                                          const float* __restrict__ Cmat,
                                          const float* __restrict__ Dvec,
                                          const float* __restrict__ steps,
                                          const float* __restrict__ W_out,
                                          const float* __restrict__ b_out) {
    __shared__ float sbuf[11264];
    const int bid = blockIdx.x, tid = threadIdx.x;

    if (bid < 16) {
        // BW[k][i] = sum_h B_part[k][h] * W_in[h][i]; 16 k-rows per block
        float* Wins = sbuf;                   // [128][64]
        float* Bs   = sbuf + DMODEL * INDIM;  // [16][128]
        for (int i = tid; i < DMODEL * INDIM; i += 256) Wins[i] = W_in[i];
        const int k0 = bid * 16;
        for (int i = tid; i < 16 * DMODEL; i += 256) {
            int kk = i >> 7, h = i & 127;
            int k = k0 + kk, p = k & 127, part = k >> 7;
            Bs[i] = Bmat[(p * DMODEL + h) * 2 + part];
        }
        __syncthreads();
        for (int e = tid; e < 16 * INDIM; e += 256) {
            int kk = e >> 6, i = e & 63;
            float acc = 0.0f;
            #pragma unroll 8
            for (int h = 0; h < DMODEL; h++) acc = fmaf(Bs[kk * DMODEL + h], Wins[h * INDIM + i], acc);
            g_BWh[(k0 + kk) * INDIM + i] = __float2half(acc);
        }
        if (bid == 0) {
            int k = tid, p = k & 127, part = k >> 7;
            float s = 0.0f;
            for (int h = 0; h < DMODEL; h++) s = fmaf(Bmat[(p * DMODEL + h) * 2 + part], b_in[h], s);
            g_BuC[k] = s;
        }
    } else if (bid < 32) {
        // Wc rows: k<128: W_out*C_re ; k<256: -W_out*C_im ; else W_out*diag(D)*W_in
        float* Wos = sbuf;                    // [64][129] padded
        float* Cs  = sbuf + OUTDIM * 129;     // [20][128]
        for (int i = tid; i < OUTDIM * DMODEL; i += 256) {
            int o = i >> 7, h = i & 127;
            Wos[o * 129 + h] = W_out[i];
        }
        const int kb0 = (bid - 16) * 20;
        for (int i = tid; i < 20 * DMODEL; i += 256) {
            int kk = i >> 7, h = i & 127;
            int k = kb0 + kk;
            float v;
            if (k < 128)      v =  Cmat[(h * DMODEL + k) * 2 + 0];
            else if (k < 256) v = -Cmat[(h * DMODEL + (k - 128)) * 2 + 1];
            else              v =  Dvec[h] * W_in[h * INDIM + (k - 256)];
            Cs[i] = v;
        }
        __syncthreads();
        for (int e = tid; e < 20 * OUTDIM; e += 256) {
            int kk = e >> 6, o = e & 63;
            float acc = 0.0f;
            #pragma unroll 8
            for (int h = 0; h < DMODEL; h++) acc = fmaf(Cs[kk * DMODEL + h], Wos[o * 129 + h], acc);
            g_WcF[o * 320 + (kb0 + kk)] = __float2half(acc);
        }
        if (bid == 16 && tid < OUTDIM) {
            float s = b_out[tid];
            for (int h = 0; h < DMODEL; h++) s = fmaf(W_out[tid * DMODEL + h] * Dvec[h], b_in[h], s);
            g_bias[tid] = s;
        }
    } else {
        // power tables Pm[j][p] = M^{j+1}; Pzw = rows (21,22)
        if (tid < DMODEL) {
            float m11, m12, m21, m22, f1, f2;
            lin_coefs(A_diag, steps, tid, m11, m12, m21, m22, f1, f2);
            float c11 = m11, c12 = m12, c21 = m21, c22 = m22;
            for (int j = 0; j < TCHUNK; j++) {
                g_Pm[j * DMODEL + tid]  = make_float4(c11, c12, c21, c22);
                g_Pzw[j * DMODEL + tid] = make_float2(c21, c22);
                float n11 = m11 * c11 + m12 * c21;
                float n12 = m11 * c12 + m12 * c22;
                float n21 = m21 * c11 + m22 * c21;
                float n22 = m21 * c12 + m22 * c22;
                c11 = n11; c12 = n12; c21 = n21; c22 = n22;
            }
        }
    }
}

// ================= kernel B: tensor-core Bu GEMM + fused chunk-local scan =================
// Per CTA (b, chunk): Bu[128 t][256 k] = x[128][64] * BW[256][64]^T (fp16 MMA, fp32 acc),
// fragments -> smem, then thread-per-chain serial scan of 128 steps.
// Dynamic smem: xh [128][72] f16 | BWh [256][72] f16 | Bus [128][264] f32
#define KB_XH    0
#define KB_BWH   18432
#define KB_BUS   55296
#define KB_SMEM  190464
#define APAD 72
#define BUSP 264
__global__ __launch_bounds__(256) void kB(const float* __restrict__ x,
                                          const float* __restrict__ A_diag,
                                          const float* __restrict__ steps) {
    extern __shared__ char dsm[];
    __half* xh  = (__half*)(dsm + KB_XH);
    __half* bwh = (__half*)(dsm + KB_BWH);
    float*  bus = (float*)(dsm + KB_BUS);

    const int b = blockIdx.x >> 5, c = blockIdx.x & 31;
    const int R0 = b * LSEQ + c * TCHUNK;
    const int tid = threadIdx.x;
    const int wid = tid >> 5, lane = tid & 31;

    // ---- stage x tile -> fp16 [128][72] ----
    {
        const float4* xg = (const float4*)(x + (size_t)R0 * INDIM);
        #pragma unroll
        for (int it = 0; it < 8; it++) {
            int idx = tid + it * 256;            // float4 index, 2048 total
            int r = idx >> 4, c4 = idx & 15;
            float4 v = xg[idx];
            __half2 h0 = __floats2half2_rn(v.x, v.y);
            __half2 h1 = __floats2half2_rn(v.z, v.w);
            *(uint2*)(xh + r * APAD + c4 * 4) =
                make_uint2(*(uint32_t*)&h0, *(uint32_t*)&h1);
        }
    }
    // ---- stage BW -> [256][72] ----
    {
        const uint4* bg = (const uint4*)g_BWh;   // 8 halves per uint4, 2048 total
        #pragma unroll
        for (int it = 0; it < 8; it++) {
            int idx = tid + it * 256;
            int r = idx >> 3, seg = idx & 7;
            *(uint4*)(bwh + r * APAD + seg * 8) = bg[idx];
        }
    }
    __syncthreads();

    // ---- GEMM1: warp wid computes rows 16*wid..+15, cols 0..255 ----
    {
        const uint32_t sX = smem_u32(xh), sW = smem_u32(bwh);
        const int q = lane >> 3, rr = lane & 7;
        const uint32_t aBase = sX + (uint32_t)(((wid * 16 + (q & 1) * 8 + rr) * APAD + (q >> 1) * 8) * 2);
        const uint32_t bBase0 = sW + (uint32_t)((((q >> 1) * 8 + rr) * APAD + (q & 1) * 8) * 2);

        float acc[32][4];
        #pragma unroll
        for (int nt = 0; nt < 32; nt++) {
            acc[nt][0] = 0.f; acc[nt][1] = 0.f; acc[nt][2] = 0.f; acc[nt][3] = 0.f;
        }
        #pragma unroll
        for (int k16 = 0; k16 < 4; k16++) {
            uint32_t a0, a1, a2, a3;
            ldsm_x4(a0, a1, a2, a3, aBase + (uint32_t)(k16 * 32));
            #pragma unroll
            for (int ntp = 0; ntp < 16; ntp++) {
                uint32_t b0, b1, b2, b3;
                ldsm_x4(b0, b1, b2, b3, bBase0 + (uint32_t)(ntp * 16 * APAD * 2 + k16 * 32));
                mma16816(acc[ntp * 2][0], acc[ntp * 2][1], acc[ntp * 2][2], acc[ntp * 2][3],
                         a0, a1, a2, a3, b0, b1);
                mma16816(acc[ntp * 2 + 1][0], acc[ntp * 2 + 1][1], acc[ntp * 2 + 1][2], acc[ntp * 2 + 1][3],
                         a0, a1, a2, a3, b2, b3);
            }
        }
        // fragments -> Bus
        const int g = lane >> 2, ci = lane & 3;
        const int row0 = wid * 16 + g;
        #pragma unroll
        for (int nt = 0; nt < 32; nt++) {
            int col = nt * 8 + ci * 2;
            *(float2*)(bus + row0 * BUSP + col)       = make_float2(acc[nt][0], acc[nt][1]);
            *(float2*)(bus + (row0 + 8) * BUSP + col) = make_float2(acc[nt][2], acc[nt][3]);
        }
    }
    __syncthreads();

    // ---- fused chunk-local scan: thread k over 128 t ----
    {
        const int k = tid, p = k & 127;
        float m11, m12, m21, m22, f1, f2;
        lin_coefs(A_diag, steps, p, m11, m12, m21, m22, f1, f2);
        const float buc = g_BuC[k];
        float z = 0.0f, w = 0.0f;
        float* wout = g_w + (size_t)R0 * CHAINS + k;
        const float* bcol = bus + k;
        for (int t = 0; t < TCHUNK; t += 4) {
            float bu[4];
            #pragma unroll
            for (int j = 0; j < 4; j++) bu[j] = bcol[(t + j) * BUSP] + buc;
            #pragma unroll
            for (int j = 0; j < 4; j++) {
                float nz = fmaf(m11, z, fmaf(m12, w, f1 * bu[j]));
                float nw = fmaf(m21, z, fmaf(m22, w, f2 * bu[j]));
                z = nz; w = nw;
                wout[(size_t)(t + j) * CHAINS] = w;
            }
        }
        g_carry[(b * NCHUNK + c) * CHAINS + k] = make_float2(z, w);
    }
}

// ================= kernel C: cross-chunk scan of carries (prefetched) =================
__global__ __launch_bounds__(256) void kC() {
    const int b = blockIdx.x, k = threadIdx.x, p = k & 127;
    const float4 mt = g_Pm[(TCHUNK - 1) * DMODEL + p];   // M^TCHUNK
    float z = 0.0f, w = 0.0f;
    for (int c0 = 0; c0 < NCHUNK; c0 += 8) {
        float2 lc[8];
        #pragma unroll
        for (int j = 0; j < 8; j++)
            lc[j] = g_carry[(b * NCHUNK + c0 + j) * CHAINS + k];
        #pragma unroll
        for (int j = 0; j < 8; j++) {
            g_cin[(b * NCHUNK + c0 + j) * CHAINS + k] = make_float2(z, w);
            float nz = fmaf(mt.x, z, fmaf(mt.y, w, lc[j].x));
            float nw = fmaf(mt.z, z, fmaf(mt.w, w, lc[j].y));
            z = nz; w = nw;
        }
    }
}

// ================= kernel D: carry fixup + output GEMM via mma.sync f16 =================
__global__ __launch_bounds__(256) void kD(const float* __restrict__ x,
                                          float* __restrict__ out) {
    __shared__ __half smA[128 * APAD];   // 18KB
    __shared__ __half smB[64 * APAD];    // 9KB
    __shared__ float czs[CHAINS], cws[CHAINS];

    const int R0 = blockIdx.x * 128;          // global row = b*LSEQ + t0
    const int b  = R0 >> 12;
    const int cc = (R0 & 4095) >> 7;          // chunk index
    const int tid = threadIdx.x;
    const int wid = tid >> 5, lane = tid & 31;

    {
        float2 ci = g_cin[(b * NCHUNK + cc) * CHAINS + tid];
        czs[tid] = ci.x; cws[tid] = ci.y;
    }

    const uint32_t sA = smem_u32(smA);
    const uint32_t sB = smem_u32(smB);

    const int q  = lane >> 3, rr = lane & 7;
    const uint32_t aBase = sA + (uint32_t)(((wid * 16 + (q & 1) * 8 + rr) * APAD + (q >> 1) * 8) * 2);
    uint32_t bBase[4];
    #pragma unroll
    for (int ntp = 0; ntp < 4; ntp++)
        bBase[ntp] = sB + (uint32_t)(((ntp * 16 + (q >> 1) * 8 + rr) * APAD + (q & 1) * 8) * 2);

    const int kp = lane;            // k-pair within slice (k = 2kp, 2kp+1)
    const int rq = wid;             // 16-row segment
    const int brow = tid >> 2, bseg = tid & 3;   // B: row o, 16-half segment

    float acc[8][4];
    #pragma unroll
    for (int nt = 0; nt < 8; nt++)
        #pragma unroll
        for (int i = 0; i < 4; i++) acc[nt][i] = 0.0f;

    for (int s = 0; s < 5; s++) {
        __syncthreads();
        // ---- stage B slice: 64 o-rows x 64 k halves ----
        {
            const uint4* src = (const uint4*)(g_WcF + brow * 320 + s * 64 + bseg * 16);
            uint4 v0 = src[0], v1 = src[1];
            uint4* dst = (uint4*)(smB + brow * APAD + bseg * 16);
            dst[0] = v0; dst[1] = v1;
        }
        // ---- stage A slice: 128 rows x 64 k, carry fixup + cvt fp16 ----
        if (s < 4) {
            const int k2 = kp * 2;
            const int kg = s * 64 + k2;
            const int p0 = kg & 127;
            const float cz0 = czs[kg],     cw0 = cws[kg];
            const float cz1 = czs[kg + 1], cw1 = cws[kg + 1];
            const float* wsrc = g_w + (size_t)R0 * CHAINS + kg;
            #pragma unroll 4
            for (int j = 0; j < 16; j++) {
                int r = rq * 16 + j;
                float4 pz = *(const float4*)(&g_Pzw[r * DMODEL + p0]);  // {z0,w0,z1,w1}
                float2 wv = *(const float2*)(wsrc + (size_t)r * CHAINS);
                float v0 = fmaf(pz.x, cz0, fmaf(pz.y, cw0, wv.x));
                float v1 = fmaf(pz.z, cz1, fmaf(pz.w, cw1, wv.y));
                *(__half2*)(smA + r * APAD + k2) = __floats2half2_rn(v0, v1);
            }
        } else {
            const int k2 = kp * 2;
            const float* xsrc = x + (size_t)R0 * INDIM + k2;
            #pragma unroll 4
            for (int j = 0; j < 16; j++) {
                int r = rq * 16 + j;
                float2 xv = *(const float2*)(xsrc + (size_t)r * INDIM);
                *(__half2*)(smA + r * APAD + k2) = __floats2half2_rn(xv.x, xv.y);
            }
        }
        __syncthreads();

        // ---- compute: 4 k16 steps ----
        #pragma unroll
        for (int k16 = 0; k16 < 4; k16++) {
            const uint32_t kofs = (uint32_t)(k16 * 16 * 2);
            uint32_t a0, a1, a2, a3;
            ldsm_x4(a0, a1, a2, a3, aBase + kofs);
            uint32_t bf[4][4];
            #pragma unroll
            for (int ntp = 0; ntp < 4; ntp++)
                ldsm_x4(bf[ntp][0], bf[ntp][1], bf[ntp][2], bf[ntp][3], bBase[ntp] + kofs);
            #pragma unroll
            for (int ntp = 0; ntp < 4; ntp++) {
                mma16816(acc[ntp * 2][0], acc[ntp * 2][1], acc[ntp * 2][2], acc[ntp * 2][3],
                         a0, a1, a2, a3, bf[ntp][0], bf[ntp][1]);
                mma16816(acc[ntp * 2 + 1][0], acc[ntp * 2 + 1][1], acc[ntp * 2 + 1][2], acc[ntp * 2 + 1][3],
                         a0, a1, a2, a3, bf[ntp][2], bf[ntp][3]);
            }
        }
    }

    // ---- epilogue: add bias, store directly from fragments ----
    const int g = lane >> 2, cpair = (lane & 3) * 2;
    const int row0 = R0 + wid * 16 + g;
    float* og0 = out + (size_t)row0 * OUTDIM;
    float* og1 = og0 + 8 * OUTDIM;
    #pragma unroll
    for (int nt = 0; nt < 8; nt++) {
        int col = nt * 8 + cpair;
        float b0 = g_bias[col], b1 = g_bias[col + 1];
        *(float2*)(og0 + col) = make_float2(acc[nt][0] + b0, acc[nt][1] + b1);
        *(float2*)(og1 + col) = make_float2(acc[nt][2] + b0, acc[nt][3] + b1);
    }
}

extern "C" void kernel_launch(void* const* d_in, const int* in_sizes, int n_in,
                              void* d_out, int out_size) {
    const float* x      = (const float*)d_in[0];
    const float* W_in   = (const float*)d_in[1];
    const float* b_in   = (const float*)d_in[2];
    const float* A_diag = (const float*)d_in[3];
    const float* Bmat   = (const float*)d_in[4];
    const float* Cmat   = (const float*)d_in[5];
    const float* Dvec   = (const float*)d_in[6];
    const float* steps  = (const float*)d_in[7];
    const float* W_out  = (const float*)d_in[8];
    const float* b_out  = (const float*)d_in[9];
    float* out = (float*)d_out;

    cudaFuncSetAttribute(kB, cudaFuncAttributeMaxDynamicSharedMemorySize, KB_SMEM);

    kA<<<33, 256>>>(W_in, b_in, A_diag, Bmat, Cmat, Dvec, steps, W_out, b_out);
    kB<<<BATCH * NCHUNK, 256, KB_SMEM>>>(x, A_diag, steps);
    kC<<<BATCH, 256>>>();
    kD<<<(BATCH * LSEQ) / TCHUNK, 256>>>(x, out);
}

// round 10
// speedup vs baseline: 3.1357x; 1.0989x over previous
#include <cuda_runtime.h>
#include <cuda_fp16.h>
#include <cstdint>
#include <cstddef>

#define BATCH   16
#define LSEQ    4096
#define INDIM   64
#define DMODEL  128
#define OUTDIM  64
#define TCHUNK  128
#define NCHUNK  32          // LSEQ / TCHUNK
#define CHAINS  256         // 128 p * {re,im}

// ---------------- device scratch (no allocations allowed) ----------------
__device__ __half g_w[(size_t)BATCH * LSEQ * CHAINS];        // local-scan w (fp16, 33.5MB)
__device__ float2 g_carry[BATCH * NCHUNK * CHAINS];          // chunk-local final states
__device__ float2 g_cin[BATCH * NCHUNK * CHAINS];            // exclusive cross-chunk prefix
__device__ __half g_BWh[CHAINS * INDIM];                     // fused B_part * W_in (fp16, [k][i])
__device__ float  g_BuC[CHAINS];                             // B_part * b_in
__device__ float4 g_Pm[TCHUNK * DMODEL];                     // M^{j+1} per p (kC uses row TCHUNK-1)
__device__ float2 g_Pzw[TCHUNK * DMODEL];                    // (M^{j+1}).{21,22} per (j,p)  [kD fixup]
__device__ __half g_WcF[OUTDIM * 320];                       // fused output matrix fp16, [o][k]
__device__ float  g_bias[OUTDIM];

// ---------------- helpers ----------------
__device__ __forceinline__ uint32_t smem_u32(const void* p) {
    uint32_t a;
    asm("{ .reg .u64 t; cvta.to.shared.u64 t, %1; cvt.u32.u64 %0, t; }" : "=r"(a) : "l"(p));
    return a;
}
__device__ __forceinline__ void ldsm_x4(uint32_t &r0, uint32_t &r1, uint32_t &r2, uint32_t &r3, uint32_t addr) {
    asm volatile("ldmatrix.sync.aligned.m8n8.x4.shared.b16 {%0,%1,%2,%3}, [%4];"
                 : "=r"(r0), "=r"(r1), "=r"(r2), "=r"(r3) : "r"(addr));
}
__device__ __forceinline__ void mma16816(float &c0, float &c1, float &c2, float &c3,
                                         uint32_t a0, uint32_t a1, uint32_t a2, uint32_t a3,
                                         uint32_t b0, uint32_t b1) {
    asm volatile("mma.sync.aligned.m16n8k16.row.col.f32.f16.f16.f32 "
                 "{%0,%1,%2,%3}, {%4,%5,%6,%7}, {%8,%9}, {%0,%1,%2,%3};"
                 : "+f"(c0), "+f"(c1), "+f"(c2), "+f"(c3)
                 : "r"(a0), "r"(a1), "r"(a2), "r"(a3), "r"(b0), "r"(b1));
}

// implicit-LinOSS per-p recurrence coefficients
__device__ __forceinline__ void lin_coefs(const float* __restrict__ A_diag,
                                          const float* __restrict__ steps, int p,
                                          float& m11, float& m12, float& m21, float& m22,
                                          float& f1, float& f2) {
    float A  = fmaxf(A_diag[p], 0.0f);
    float dt = 1.0f / (1.0f + expf(-steps[p]));
    float dt2A = dt * dt * A;
    float S  = 1.0f / (1.0f + dt2A);
    m11 = 1.0f - dt2A * S;
    m12 = -dt * A * S;
    m21 = dt * S;
    m22 = S;
    f1  = m11 * dt;
    f2  = m21 * dt;
}

// ================= kernel A: build fused matrices + power tables =================
__global__ __launch_bounds__(256) void kA(const float* __restrict__ W_in,
                                          const float* __restrict__ b_in,
                                          const float* __restrict__ A_diag,
                                          const float* __restrict__ Bmat,
                                          const float* __restrict__ Cmat,
                                          const float* __restrict__ Dvec,
                                          const float* __restrict__ steps,
                                          const float* __restrict__ W_out,
                                          const float* __restrict__ b_out) {
    __shared__ float sbuf[11264];
    const int bid = blockIdx.x, tid = threadIdx.x;

    if (bid < 16) {
        // BW[k][i] = sum_h B_part[k][h] * W_in[h][i]; 16 k-rows per block
        float* Wins = sbuf;                   // [128][64]
        float* Bs   = sbuf + DMODEL * INDIM;  // [16][128]
        for (int i = tid; i < DMODEL * INDIM; i += 256) Wins[i] = W_in[i];
        const int k0 = bid * 16;
        for (int i = tid; i < 16 * DMODEL; i += 256) {
            int kk = i >> 7, h = i & 127;
            int k = k0 + kk, p = k & 127, part = k >> 7;
            Bs[i] = Bmat[(p * DMODEL + h) * 2 + part];
        }
        __syncthreads();
        for (int e = tid; e < 16 * INDIM; e += 256) {
            int kk = e >> 6, i = e & 63;
            float acc = 0.0f;
            #pragma unroll 8
            for (int h = 0; h < DMODEL; h++) acc = fmaf(Bs[kk * DMODEL + h], Wins[h * INDIM + i], acc);
            g_BWh[(k0 + kk) * INDIM + i] = __float2half(acc);
        }
        if (bid == 0) {
            int k = tid, p = k & 127, part = k >> 7;
            float s = 0.0f;
            for (int h = 0; h < DMODEL; h++) s = fmaf(Bmat[(p * DMODEL + h) * 2 + part], b_in[h], s);
            g_BuC[k] = s;
        }
    } else if (bid < 32) {
        // Wc rows: k<128: W_out*C_re ; k<256: -W_out*C_im ; else W_out*diag(D)*W_in
        float* Wos = sbuf;                    // [64][129] padded
        float* Cs  = sbuf + OUTDIM * 129;     // [20][128]
        for (int i = tid; i < OUTDIM * DMODEL; i += 256) {
            int o = i >> 7, h = i & 127;
            Wos[o * 129 + h] = W_out[i];
        }
        const int kb0 = (bid - 16) * 20;
        for (int i = tid; i < 20 * DMODEL; i += 256) {
            int kk = i >> 7, h = i & 127;
            int k = kb0 + kk;
            float v;
            if (k < 128)      v =  Cmat[(h * DMODEL + k) * 2 + 0];
            else if (k < 256) v = -Cmat[(h * DMODEL + (k - 128)) * 2 + 1];
            else              v =  Dvec[h] * W_in[h * INDIM + (k - 256)];
            Cs[i] = v;
        }
        __syncthreads();
        for (int e = tid; e < 20 * OUTDIM; e += 256) {
            int kk = e >> 6, o = e & 63;
            float acc = 0.0f;
            #pragma unroll 8
            for (int h = 0; h < DMODEL; h++) acc = fmaf(Cs[kk * DMODEL + h], Wos[o * 129 + h], acc);
            g_WcF[o * 320 + (kb0 + kk)] = __float2half(acc);
        }
        if (bid == 16 && tid < OUTDIM) {
            float s = b_out[tid];
            for (int h = 0; h < DMODEL; h++) s = fmaf(W_out[tid * DMODEL + h] * Dvec[h], b_in[h], s);
            g_bias[tid] = s;
        }
    } else {
        // power tables Pm[j][p] = M^{j+1}; Pzw = rows (21,22)
        if (tid < DMODEL) {
            float m11, m12, m21, m22, f1, f2;
            lin_coefs(A_diag, steps, tid, m11, m12, m21, m22, f1, f2);
            float c11 = m11, c12 = m12, c21 = m21, c22 = m22;
            for (int j = 0; j < TCHUNK; j++) {
                g_Pm[j * DMODEL + tid]  = make_float4(c11, c12, c21, c22);
                g_Pzw[j * DMODEL + tid] = make_float2(c21, c22);
                float n11 = m11 * c11 + m12 * c21;
                float n12 = m11 * c12 + m12 * c22;
                float n21 = m21 * c11 + m22 * c21;
                float n22 = m21 * c12 + m22 * c22;
                c11 = n11; c12 = n12; c21 = n21; c22 = n22;
            }
        }
    }
}

// ================= kernel B: tensor-core Bu GEMM + fused chunk-local scan =================
// Per CTA (b, chunk): Bu[128 t][256 k] = x[128][64] * BW[256][64]^T (fp16 MMA, fp32 acc),
// fragments -> smem, then thread-per-chain serial scan of 128 steps, w stored fp16.
// Dynamic smem: xh [128][72] f16 | BWh [256][72] f16 | Bus [128][264] f32
#define KB_XH    0
#define KB_BWH   18432
#define KB_BUS   55296
#define KB_SMEM  190464
#define APAD 72
#define BUSP 264
__global__ __launch_bounds__(256) void kB(const float* __restrict__ x,
                                          const float* __restrict__ A_diag,
                                          const float* __restrict__ steps) {
    extern __shared__ char dsm[];
    __half* xh  = (__half*)(dsm + KB_XH);
    __half* bwh = (__half*)(dsm + KB_BWH);
    float*  bus = (float*)(dsm + KB_BUS);

    const int b = blockIdx.x >> 5, c = blockIdx.x & 31;
    const int R0 = b * LSEQ + c * TCHUNK;
    const int tid = threadIdx.x;
    const int wid = tid >> 5, lane = tid & 31;

    // ---- stage x tile -> fp16 [128][72] ----
    {
        const float4* xg = (const float4*)(x + (size_t)R0 * INDIM);
        #pragma unroll
        for (int it = 0; it < 8; it++) {
            int idx = tid + it * 256;            // float4 index, 2048 total
            int r = idx >> 4, c4 = idx & 15;
            float4 v = xg[idx];
            __half2 h0 = __floats2half2_rn(v.x, v.y);
            __half2 h1 = __floats2half2_rn(v.z, v.w);
            *(uint2*)(xh + r * APAD + c4 * 4) =
                make_uint2(*(uint32_t*)&h0, *(uint32_t*)&h1);
        }
    }
    // ---- stage BW -> [256][72] ----
    {
        const uint4* bg = (const uint4*)g_BWh;   // 8 halves per uint4, 2048 total
        #pragma unroll
        for (int it = 0; it < 8; it++) {
            int idx = tid + it * 256;
            int r = idx >> 3, seg = idx & 7;
            *(uint4*)(bwh + r * APAD + seg * 8) = bg[idx];
        }
    }
    __syncthreads();

    // ---- GEMM1: warp wid computes rows 16*wid..+15, cols 0..255 ----
    {
        const uint32_t sX = smem_u32(xh), sW = smem_u32(bwh);
        const int q = lane >> 3, rr = lane & 7;
        const uint32_t aBase = sX + (uint32_t)(((wid * 16 + (q & 1) * 8 + rr) * APAD + (q >> 1) * 8) * 2);
        const uint32_t bBase0 = sW + (uint32_t)((((q >> 1) * 8 + rr) * APAD + (q & 1) * 8) * 2);

        float acc[32][4];
        #pragma unroll
        for (int nt = 0; nt < 32; nt++) {
            acc[nt][0] = 0.f; acc[nt][1] = 0.f; acc[nt][2] = 0.f; acc[nt][3] = 0.f;
        }
        #pragma unroll
        for (int k16 = 0; k16 < 4; k16++) {
            uint32_t a0, a1, a2, a3;
            ldsm_x4(a0, a1, a2, a3, aBase + (uint32_t)(k16 * 32));
            #pragma unroll
            for (int ntp = 0; ntp < 16; ntp++) {
                uint32_t b0, b1, b2, b3;
                ldsm_x4(b0, b1, b2, b3, bBase0 + (uint32_t)(ntp * 16 * APAD * 2 + k16 * 32));
                mma16816(acc[ntp * 2][0], acc[ntp * 2][1], acc[ntp * 2][2], acc[ntp * 2][3],
                         a0, a1, a2, a3, b0, b1);
                mma16816(acc[ntp * 2 + 1][0], acc[ntp * 2 + 1][1], acc[ntp * 2 + 1][2], acc[ntp * 2 + 1][3],
                         a0, a1, a2, a3, b2, b3);
            }
        }
        // fragments -> Bus
        const int g = lane >> 2, ci = lane & 3;
        const int row0 = wid * 16 + g;
        #pragma unroll
        for (int nt = 0; nt < 32; nt++) {
            int col = nt * 8 + ci * 2;
            *(float2*)(bus + row0 * BUSP + col)       = make_float2(acc[nt][0], acc[nt][1]);
            *(float2*)(bus + (row0 + 8) * BUSP + col) = make_float2(acc[nt][2], acc[nt][3]);
        }
    }
    __syncthreads();

    // ---- fused chunk-local scan: thread k over 128 t, fp16 w stores ----
    {
        const int k = tid, p = k & 127;
        float m11, m12, m21, m22, f1, f2;
        lin_coefs(A_diag, steps, p, m11, m12, m21, m22, f1, f2);
        const float buc = g_BuC[k];
        float z = 0.0f, w = 0.0f;
        __half* wout = g_w + (size_t)R0 * CHAINS + k;
        const float* bcol = bus + k;
        for (int t = 0; t < TCHUNK; t += 4) {
            float bu[4];
            #pragma unroll
            for (int j = 0; j < 4; j++) bu[j] = bcol[(t + j) * BUSP] + buc;
            #pragma unroll
            for (int j = 0; j < 4; j++) {
                float nz = fmaf(m11, z, fmaf(m12, w, f1 * bu[j]));
                float nw = fmaf(m21, z, fmaf(m22, w, f2 * bu[j]));
                z = nz; w = nw;
                wout[(size_t)(t + j) * CHAINS] = __float2half(w);
            }
        }
        g_carry[(b * NCHUNK + c) * CHAINS + k] = make_float2(z, w);
    }
}

// ================= kernel C: cross-chunk scan of carries (prefetched) =================
__global__ __launch_bounds__(256) void kC() {
    const int b = blockIdx.x, k = threadIdx.x, p = k & 127;
    const float4 mt = g_Pm[(TCHUNK - 1) * DMODEL + p];   // M^TCHUNK
    float z = 0.0f, w = 0.0f;
    for (int c0 = 0; c0 < NCHUNK; c0 += 8) {
        float2 lc[8];
        #pragma unroll
        for (int j = 0; j < 8; j++)
            lc[j] = g_carry[(b * NCHUNK + c0 + j) * CHAINS + k];
        #pragma unroll
        for (int j = 0; j < 8; j++) {
            g_cin[(b * NCHUNK + c0 + j) * CHAINS + k] = make_float2(z, w);
            float nz = fmaf(mt.x, z, fmaf(mt.y, w, lc[j].x));
            float nw = fmaf(mt.z, z, fmaf(mt.w, w, lc[j].y));
            z = nz; w = nw;
        }
    }
}

// ================= kernel D: carry fixup + output GEMM via mma.sync f16 =================
__global__ __launch_bounds__(256) void kD(const float* __restrict__ x,
                                          float* __restrict__ out) {
    __shared__ __half smA[128 * APAD];   // 18KB
    __shared__ __half smB[64 * APAD];    // 9KB
    __shared__ float czs[CHAINS], cws[CHAINS];

    const int R0 = blockIdx.x * 128;          // global row = b*LSEQ + t0
    const int b  = R0 >> 12;
    const int cc = (R0 & 4095) >> 7;          // chunk index
    const int tid = threadIdx.x;
    const int wid = tid >> 5, lane = tid & 31;

    {
        float2 ci = g_cin[(b * NCHUNK + cc) * CHAINS + tid];
        czs[tid] = ci.x; cws[tid] = ci.y;
    }

    const uint32_t sA = smem_u32(smA);
    const uint32_t sB = smem_u32(smB);

    const int q  = lane >> 3, rr = lane & 7;
    const uint32_t aBase = sA + (uint32_t)(((wid * 16 + (q & 1) * 8 + rr) * APAD + (q >> 1) * 8) * 2);
    uint32_t bBase[4];
    #pragma unroll
    for (int ntp = 0; ntp < 4; ntp++)
        bBase[ntp] = sB + (uint32_t)(((ntp * 16 + (q >> 1) * 8 + rr) * APAD + (q & 1) * 8) * 2);

    const int kp = lane;            // k-pair within slice (k = 2kp, 2kp+1)
    const int rq = wid;             // 16-row segment
    const int brow = tid >> 2, bseg = tid & 3;   // B: row o, 16-half segment

    float acc[8][4];
    #pragma unroll
    for (int nt = 0; nt < 8; nt++)
        #pragma unroll
        for (int i = 0; i < 4; i++) acc[nt][i] = 0.0f;

    for (int s = 0; s < 5; s++) {
        __syncthreads();
        // ---- stage B slice: 64 o-rows x 64 k halves ----
        {
            const uint4* src = (const uint4*)(g_WcF + brow * 320 + s * 64 + bseg * 16);
            uint4 v0 = src[0], v1 = src[1];
            uint4* dst = (uint4*)(smB + brow * APAD + bseg * 16);
            dst[0] = v0; dst[1] = v1;
        }
        // ---- stage A slice: 128 rows x 64 k, fp16 w load + fp32 fixup + cvt fp16 ----
        if (s < 4) {
            const int k2 = kp * 2;
            const int kg = s * 64 + k2;
            const int p0 = kg & 127;
            const float cz0 = czs[kg],     cw0 = cws[kg];
            const float cz1 = czs[kg + 1], cw1 = cws[kg + 1];
            const __half* wsrc = g_w + (size_t)R0 * CHAINS + kg;
            #pragma unroll 4
            for (int j = 0; j < 16; j++) {
                int r = rq * 16 + j;
                float4 pz = *(const float4*)(&g_Pzw[r * DMODEL + p0]);  // {z0,w0,z1,w1}
                __half2 wh = *(const __half2*)(wsrc + (size_t)r * CHAINS);
                float2 wf = __half22float2(wh);
                float v0 = fmaf(pz.x, cz0, fmaf(pz.y, cw0, wf.x));
                float v1 = fmaf(pz.z, cz1, fmaf(pz.w, cw1, wf.y));
                *(__half2*)(smA + r * APAD + k2) = __floats2half2_rn(v0, v1);
            }
        } else {
            const int k2 = kp * 2;
            const float* xsrc = x + (size_t)R0 * INDIM + k2;
            #pragma unroll 4
            for (int j = 0; j < 16; j++) {
                int r = rq * 16 + j;
                float2 xv = *(const float2*)(xsrc + (size_t)r * INDIM);
                *(__half2*)(smA + r * APAD + k2) = __floats2half2_rn(xv.x, xv.y);
            }
        }
        __syncthreads();

        // ---- compute: 4 k16 steps ----
        #pragma unroll
        for (int k16 = 0; k16 < 4; k16++) {
            const uint32_t kofs = (uint32_t)(k16 * 16 * 2);
            uint32_t a0, a1, a2, a3;
            ldsm_x4(a0, a1, a2, a3, aBase + kofs);
            uint32_t bf[4][4];
            #pragma unroll
            for (int ntp = 0; ntp < 4; ntp++)
                ldsm_x4(bf[ntp][0], bf[ntp][1], bf[ntp][2], bf[ntp][3], bBase[ntp] + kofs);
            #pragma unroll
            for (int ntp = 0; ntp < 4; ntp++) {
                mma16816(acc[ntp * 2][0], acc[ntp * 2][1], acc[ntp * 2][2], acc[ntp * 2][3],
                         a0, a1, a2, a3, bf[ntp][0], bf[ntp][1]);
                mma16816(acc[ntp * 2 + 1][0], acc[ntp * 2 + 1][1], acc[ntp * 2 + 1][2], acc[ntp * 2 + 1][3],
                         a0, a1, a2, a3, bf[ntp][2], bf[ntp][3]);
            }
        }
    }

    // ---- epilogue: add bias, store directly from fragments ----
    const int g = lane >> 2, cpair = (lane & 3) * 2;
    const int row0 = R0 + wid * 16 + g;
    float* og0 = out + (size_t)row0 * OUTDIM;
    float* og1 = og0 + 8 * OUTDIM;
    #pragma unroll
    for (int nt = 0; nt < 8; nt++) {
        int col = nt * 8 + cpair;
        float b0 = g_bias[col], b1 = g_bias[col + 1];
        *(float2*)(og0 + col) = make_float2(acc[nt][0] + b0, acc[nt][1] + b1);
        *(float2*)(og1 + col) = make_float2(acc[nt][2] + b0, acc[nt][3] + b1);
    }
}

extern "C" void kernel_launch(void* const* d_in, const int* in_sizes, int n_in,
                              void* d_out, int out_size) {
    const float* x      = (const float*)d_in[0];
    const float* W_in   = (const float*)d_in[1];
    const float* b_in   = (const float*)d_in[2];
    const float* A_diag = (const float*)d_in[3];
    const float* Bmat   = (const float*)d_in[4];
    const float* Cmat   = (const float*)d_in[5];
    const float* Dvec   = (const float*)d_in[6];
    const float* steps  = (const float*)d_in[7];
    const float* W_out  = (const float*)d_in[8];
    const float* b_out  = (const float*)d_in[9];
    float* out = (float*)d_out;

    cudaFuncSetAttribute(kB, cudaFuncAttributeMaxDynamicSharedMemorySize, KB_SMEM);

    kA<<<33, 256>>>(W_in, b_in, A_diag, Bmat, Cmat, Dvec, steps, W_out, b_out);
    kB<<<BATCH * NCHUNK, 256, KB_SMEM>>>(x, A_diag, steps);
    kC<<<BATCH, 256>>>();
    kD<<<(BATCH * LSEQ) / TCHUNK, 256>>>(x, out);
}